// round 14
// baseline (speedup 1.0000x reference)
#include <cuda_runtime.h>
#include <math.h>

#define B_    64
#define L_    4096
#define DIN   64
#define L1C   4093
#define L2C   4086
#define L3C   4071
#define HID   256
#define G4    1024
#define TDEC  60
#define CH    2036
#define NBLK  128u
#define WS1   292
#define XS1   292
#define WS2   260
#define XS2   260

__device__ float g_y1 [B_*L1C*8];
__device__ float g_y2 [B_*L2C*16];
__device__ float g_enc[B_*L3C*32];
__device__ float g_h1p[2][2*B_*HID];
__device__ float g_part[2*64*2*34];
__device__ float g_d2in[B_*TDEC*512];
__device__ float g_ig [2*B_*TDEC*G4];
__device__ float g_h2p[2][2*B_*HID];
__device__ float g_l0 [B_*TDEC*512];
__device__ float g_l1 [B_*TDEC*512];
__device__ unsigned g_bc1, g_bc2a, g_bc2b;

__device__ __forceinline__ void gridbar(unsigned* ctr, unsigned target){
    __syncthreads();
    if (threadIdx.x == 0){
        asm volatile("red.release.gpu.global.add.u32 [%0], 1;" :: "l"(ctr) : "memory");
        unsigned v;
        do { asm volatile("ld.acquire.gpu.global.u32 %0, [%1];" : "=r"(v) : "l"(ctr) : "memory"); } while (v < target);
    }
    __syncthreads();
}

__device__ __forceinline__ float sigm(float x){ return 1.f/(1.f+__expf(-x)); }
__device__ __forceinline__ unsigned long long pk2(float x, float y){
    unsigned long long r; asm("mov.b64 %0, {%1, %2};" : "=l"(r) : "f"(x), "f"(y)); return r;
}
__device__ __forceinline__ void upk2(unsigned long long v, float &x, float &y){
    asm("mov.b64 {%0, %1}, %2;" : "=f"(x), "=f"(y) : "l"(v));
}
__device__ __forceinline__ void ffma2(unsigned long long &c, unsigned long long a, unsigned long long b){
    asm("fma.rn.f32x2 %0, %1, %2, %0;" : "+l"(c) : "l"(a), "l"(b));
}
__device__ __forceinline__ unsigned long long mul2(unsigned long long a, unsigned long long b){
    unsigned long long r; asm("mul.rn.f32x2 %0, %1, %2;" : "=l"(r) : "l"(a), "l"(b)); return r;
}
__device__ __forceinline__ float red2(unsigned long long v){
    float lo, hi; upk2(v, lo, hi); return lo + hi;
}

// ---------- conv1 ----------
__global__ void __launch_bounds__(256) conv1_kernel(const float* __restrict__ x,
        const float* __restrict__ w, const float* __restrict__ bias){
    if (blockIdx.x == 0 && blockIdx.y == 0 && threadIdx.x == 0){
        g_bc1 = 0u; g_bc2a = 0u; g_bc2b = 0u;
    }
    __shared__ __align__(16) float xs[131*68];
    __shared__ __align__(16) float ws[32*68];
    int b = blockIdx.y, l0 = blockIdx.x*128, tid = threadIdx.x;
    for (int i = tid; i < 2048; i += 256){
        int o = i>>8, ii = (i>>2)&63, t = i&3;
        ws[(t*8+o)*68+ii] = w[i];
    }
    for (int i = tid; i < 131*64; i += 256){
        int p = i>>6, c = i&63, l = l0+p;
        xs[p*68+c] = (l < L_) ? x[(b*L_+l)*DIN+c] : 0.f;
    }
    __syncthreads();
    for (int oi = 0; oi < 4; oi++){
        int idx = tid + oi*256;
        int l = idx>>3, o = idx&7, gl = l0+l;
        if (gl >= L1C) continue;
        unsigned long long acc = pk2(bias[o], 0.f);
        #pragma unroll
        for (int t = 0; t < 4; t++){
            const ulonglong2* xp = (const ulonglong2*)&xs[(l+t)*68];
            const ulonglong2* wp = (const ulonglong2*)&ws[(t*8+o)*68];
            #pragma unroll
            for (int q = 0; q < 16; q++){
                ulonglong2 xv = xp[q], wv = wp[q];
                ffma2(acc, wv.x, xv.x);
                ffma2(acc, wv.y, xv.y);
            }
        }
        g_y1[(b*L1C+gl)*8+o] = fmaxf(red2(acc), 0.f);
    }
}

// ---------- conv2 ----------
__global__ void __launch_bounds__(256) conv2_kernel(const float* __restrict__ w,
        const float* __restrict__ bias){
    __shared__ __align__(16) float xs[263*8];
    __shared__ __align__(16) float ws[128*12];
    int b = blockIdx.y, l0 = blockIdx.x*256, tid = threadIdx.x;
    for (int i = tid; i < 1024; i += 256){
        int o = i>>6, ii = (i>>3)&7, t = i&7;
        ws[(t*16+o)*12+ii] = w[i];
    }
    for (int i = tid; i < 263*8; i += 256){
        int p = i>>3, c = i&7, l = l0+p;
        xs[i] = (l < L1C) ? g_y1[(b*L1C+l)*8+c] : 0.f;
    }
    __syncthreads();
    for (int oi = 0; oi < 16; oi++){
        int idx = tid + oi*256;
        int l = idx>>4, o = idx&15, gl = l0+l;
        if (gl >= L2C) continue;
        unsigned long long acc = pk2(bias[o], 0.f);
        #pragma unroll
        for (int t = 0; t < 8; t++){
            const ulonglong2* xp = (const ulonglong2*)&xs[(l+t)*8];
            const ulonglong2* wp = (const ulonglong2*)&ws[(t*16+o)*12];
            ulonglong2 x0 = xp[0], x1 = xp[1], w0 = wp[0], w1 = wp[1];
            ffma2(acc, w0.x, x0.x); ffma2(acc, w0.y, x0.y);
            ffma2(acc, w1.x, x1.x); ffma2(acc, w1.y, x1.y);
        }
        g_y2[(b*L2C+gl)*16+o] = fmaxf(red2(acc), 0.f);
    }
}

// ---------- conv3 ----------
__global__ void __launch_bounds__(256) conv3_kernel(const float* __restrict__ w,
        const float* __restrict__ bias){
    __shared__ __align__(16) float xs[143*20+4];
    __shared__ __align__(16) float4 ws4[64*32];
    __shared__ float bsm[32];
    int b = blockIdx.y, l0 = blockIdx.x*128, tid = threadIdx.x;
    for (int i = tid; i < 2048; i += 256){
        int o = i >> 6, tq = i & 63, t = tq >> 2, q = tq & 3;
        float4 v;
        v.x = w[o*256 + (q*4+0)*16 + t];
        v.y = w[o*256 + (q*4+1)*16 + t];
        v.z = w[o*256 + (q*4+2)*16 + t];
        v.w = w[o*256 + (q*4+3)*16 + t];
        ws4[tq*32 + o] = v;
    }
    for (int i = tid; i < 143*16; i += 256){
        int p = i >> 4, c = i & 15, l = l0 + p;
        xs[p*20 + c] = (l < L2C) ? g_y2[(b*L2C+l)*16+c] : 0.f;
    }
    if (tid < 32) bsm[tid] = bias[tid];
    __syncthreads();
    int og = tid & 7, lg = tid >> 3;
    unsigned long long acc[4][4];
    #pragma unroll
    for (int i = 0; i < 4; i++)
        #pragma unroll
        for (int j = 0; j < 4; j++) acc[i][j] = pk2(0.f, 0.f);
    for (int t = 0; t < 16; t++){
        #pragma unroll
        for (int q = 0; q < 4; q++){
            int tq = t*4+q;
            ulonglong2 wv[4], xv[4];
            #pragma unroll
            for (int i = 0; i < 4; i++) wv[i] = *(const ulonglong2*)&ws4[tq*32 + og + i*8];
            #pragma unroll
            for (int j = 0; j < 4; j++) xv[j] = *(const ulonglong2*)&xs[(lg + 32*j + t)*20 + q*4];
            #pragma unroll
            for (int i = 0; i < 4; i++)
                #pragma unroll
                for (int j = 0; j < 4; j++){
                    ffma2(acc[i][j], wv[i].x, xv[j].x);
                    ffma2(acc[i][j], wv[i].y, xv[j].y);
                }
        }
    }
    #pragma unroll
    for (int i = 0; i < 4; i++){
        int o = og + i*8;
        #pragma unroll
        for (int j = 0; j < 4; j++){
            int gl = l0 + lg + 32*j;
            if (gl < L3C)
                g_enc[((size_t)b*L3C+gl)*32+o] = fmaxf(red2(acc[i][j]) + bsm[o], 0.f);
        }
    }
}

// ---------- dec1 persistent: 512 threads, K-split cell ----------
#define D1P_FL (64*WS1+8192+16*XS1+1088+1088+1088+64+256+64)
#define D1P_SMEM (D1P_FL*4)
__global__ void __launch_bounds__(512,1) dec1_persist(const float* __restrict__ attn_w,
        const float* __restrict__ wih, const float* __restrict__ whh,
        const float* __restrict__ bih, const float* __restrict__ bhh){
    extern __shared__ __align__(16) float sm[];
    float* ws    = sm;
    float* aw    = ws + 64*WS1;
    float* xin   = aw + 8192;
    float* gbuf  = xin + 16*XS1;
    float* gbuf2 = gbuf + 1088;
    float* wred  = gbuf2 + 1088;
    float* us    = wred + 1088;
    float* cs    = us + 64;
    float* bs    = cs + 256;
    int tid = threadIdx.x, bid = blockIdx.x;
    int ab = bid >> 1, ah = bid & 1;
    int u0 = (bid & 15)*16, bg = (bid>>4)&3, d = bid>>6, b0 = bg*16;

    const float* wih_d = wih + d*G4*32;
    const float* whh_d = whh + d*G4*HID;
    for (int i = tid; i < 64*288; i += 512){
        int r = i/288, k = i-r*288;
        int gate = (r>>4)*HID + u0 + (r&15);
        ws[r*WS1+k] = (k < 32) ? wih_d[gate*32+k] : whh_d[gate*HID+k-32];
    }
    for (int i = tid; i < 8192; i += 512) aw[i] = attn_w[i];
    if (tid < 64){
        int gate = (tid>>4)*HID + u0 + (tid&15);
        bs[tid] = bih[d*G4+gate] + bhh[d*G4+gate];
    }
    if (tid < 256) cs[tid] = 0.f;
    __syncthreads();

    unsigned bt = 0;
    const float* encb = g_enc + (size_t)ab*(L3C*32);
    int lo = ah*CH, hi = (lo+CH < L3C) ? lo+CH : L3C;
    int chh = tid & 1, lslice = tid >> 1;

    for (int t = 0; t < TDEC; t++){
        const float* hprev = g_h1p[(t+1)&1];
        {
            int dd = tid>>8, rem = tid&255, c = rem&31, kp = rem>>5;
            float acc = 0.f;
            if (t > 0){
                const float* h = hprev + dd*B_*HID + ab*HID + kp*32;
                const float* awp = aw + kp*32*32 + c;
                #pragma unroll 8
                for (int k = 0; k < 32; k++) acc += __ldcg(h+k)*awp[k*32];
            }
            gbuf[tid] = acc;
        }
        __syncthreads();
        if (tid < 64){
            int dd = tid>>5, c = tid&31;
            float s = 0.f;
            #pragma unroll
            for (int j = 0; j < 8; j++) s += gbuf[dd*256 + j*32 + c];
            us[tid] = s;
        }
        __syncthreads();
        unsigned long long uf[8], ub[8];
        {
            const unsigned long long* ufp = (const unsigned long long*)&us[chh*16];
            const unsigned long long* ubp = (const unsigned long long*)&us[32 + chh*16];
            #pragma unroll
            for (int i = 0; i < 8; i++){ uf[i] = ufp[i]; ub[i] = ubp[i]; }
        }
        float mf = -1e30f, mb = -1e30f, sf = 0.f, sb = 0.f;
        unsigned long long vf2[8], vb2[8];
        #pragma unroll
        for (int i = 0; i < 8; i++){ vf2[i] = pk2(0.f,0.f); vb2[i] = vf2[i]; }
        #pragma unroll 2
        for (int it = 0; it < 8; it++){
            int l = lo + lslice + it*256;
            bool valid = (l < hi);
            ulonglong2 ev2[4];
            if (valid){
                const ulonglong2* e2 = (const ulonglong2*)(encb + l*32 + chh*16);
                #pragma unroll
                for (int j = 0; j < 4; j++) ev2[j] = e2[j];
            } else {
                #pragma unroll
                for (int j = 0; j < 4; j++){ ev2[j].x = 0ull; ev2[j].y = 0ull; }
            }
            unsigned long long dA = pk2(0.f,0.f), dB = dA;
            #pragma unroll
            for (int j = 0; j < 4; j++){
                ffma2(dA, ev2[j].x, uf[2*j]);   ffma2(dA, ev2[j].y, uf[2*j+1]);
                ffma2(dB, ev2[j].x, ub[2*j]);   ffma2(dB, ev2[j].y, ub[2*j+1]);
            }
            float df = red2(dA); df += __shfl_xor_sync(0xffffffffu, df, 1);
            float db = red2(dB); db += __shfl_xor_sync(0xffffffffu, db, 1);
            if (!valid){ df = -1e30f; db = -1e30f; }
            if (df > mf){
                float sc = __expf(mf-df); sf *= sc;
                unsigned long long sc2 = pk2(sc,sc);
                #pragma unroll
                for (int i = 0; i < 8; i++) vf2[i] = mul2(vf2[i], sc2);
                mf = df;
            }
            float pf = __expf(df-mf); sf += pf;
            unsigned long long pf2 = pk2(pf,pf);
            #pragma unroll
            for (int j = 0; j < 4; j++){
                ffma2(vf2[2*j],   pf2, ev2[j].x);
                ffma2(vf2[2*j+1], pf2, ev2[j].y);
            }
            if (db > mb){
                float sc = __expf(mb-db); sb *= sc;
                unsigned long long sc2 = pk2(sc,sc);
                #pragma unroll
                for (int i = 0; i < 8; i++) vb2[i] = mul2(vb2[i], sc2);
                mb = db;
            }
            float pb = __expf(db-mb); sb += pb;
            unsigned long long pb2 = pk2(pb,pb);
            #pragma unroll
            for (int j = 0; j < 4; j++){
                ffma2(vb2[2*j],   pb2, ev2[j].x);
                ffma2(vb2[2*j+1], pb2, ev2[j].y);
            }
        }
        #pragma unroll
        for (int off = 2; off <= 16; off <<= 1){
            float mo = __shfl_xor_sync(0xffffffffu, mf, off);
            float so = __shfl_xor_sync(0xffffffffu, sf, off);
            float M = fmaxf(mf, mo); float ea=__expf(mf-M), eb=__expf(mo-M);
            unsigned long long ea2 = pk2(ea,ea), eb2 = pk2(eb,eb);
            sf = sf*ea + so*eb;
            #pragma unroll
            for (int i = 0; i < 8; i++){
                unsigned long long vo = __shfl_xor_sync(0xffffffffu, vf2[i], off);
                vf2[i] = mul2(vf2[i], ea2); ffma2(vf2[i], eb2, vo);
            }
            mf = M;
            mo = __shfl_xor_sync(0xffffffffu, mb, off);
            so = __shfl_xor_sync(0xffffffffu, sb, off);
            M = fmaxf(mb, mo); ea=__expf(mb-M); eb=__expf(mo-M);
            ea2 = pk2(ea,ea); eb2 = pk2(eb,eb);
            sb = sb*ea + so*eb;
            #pragma unroll
            for (int i = 0; i < 8; i++){
                unsigned long long vo = __shfl_xor_sync(0xffffffffu, vb2[i], off);
                vb2[i] = mul2(vb2[i], ea2); ffma2(vb2[i], eb2, vo);
            }
            mb = M;
        }
        {
            int lane = tid & 31, wq = tid >> 5;
            float* p = wred + wq*68;
            if (lane < 2){
                if (lane == 0){ p[0]=mf; p[1]=sf; p[34]=mb; p[35]=sb; }
                float* v0 = p + 2 + chh*16;
                float* v1 = p + 36 + chh*16;
                #pragma unroll
                for (int i = 0; i < 8; i++){
                    float lo2, hi2;
                    upk2(vf2[i], lo2, hi2); v0[i*2]=lo2; v0[i*2+1]=hi2;
                    upk2(vb2[i], lo2, hi2); v1[i*2]=lo2; v1[i*2+1]=hi2;
                }
            }
        }
        __syncthreads();
        if (tid < 32){
            #pragma unroll
            for (int dir = 0; dir < 2; dir++){
                float M=-1e30f, S=0.f, V=0.f;
                #pragma unroll
                for (int j = 0; j < 16; j++){
                    const float* p = wred + j*68 + dir*34;
                    float mj=p[0], sj=p[1], vj=p[2+tid];
                    float nM=fmaxf(M,mj); float ea=__expf(M-nM), eb=__expf(mj-nM);
                    V=V*ea+vj*eb; S=S*ea+sj*eb; M=nM;
                }
                int pb2i = ((dir*64+ab)*2+ah)*34;
                __stcg(&g_part[pb2i+2+tid], V);
                if (tid == 0){ __stcg(&g_part[pb2i], M); __stcg(&g_part[pb2i+1], S); }
            }
        }
        bt += NBLK; gridbar(&g_bc1, bt);

        for (int i = tid; i < 16*288; i += 512){
            int bb = i/288, k = i-bb*288; float v;
            if (k < 32){
                int b = b0+bb;
                const float* p0 = &g_part[((d*64+b)*2+0)*34];
                const float* p1 = p0 + 34;
                float m0=__ldcg(p0), s0=__ldcg(p0+1), v0=__ldcg(p0+2+k);
                float m1=__ldcg(p1), s1=__ldcg(p1+1), v1=__ldcg(p1+2+k);
                float M=fmaxf(m0,m1); float e0=__expf(m0-M), e1=__expf(m1-M);
                v = (v0*e0+v1*e1)/(s0*e0+s1*e1);
            } else {
                v = (t > 0) ? __ldcg(&hprev[d*B_*HID+(b0+bb)*HID+k-32]) : 0.f;
            }
            xin[bb*XS1 + k] = v;
        }
        __syncthreads();
        {
            int ks = tid >> 8, rem = tid & 255;
            int b = rem & 15, rg = rem >> 4, r0 = rg*4;
            unsigned long long A0 = ks ? pk2(0.f,0.f) : pk2(bs[r0],   0.f);
            unsigned long long A1 = ks ? pk2(0.f,0.f) : pk2(bs[r0+1], 0.f);
            unsigned long long A2 = ks ? pk2(0.f,0.f) : pk2(bs[r0+2], 0.f);
            unsigned long long A3 = ks ? pk2(0.f,0.f) : pk2(bs[r0+3], 0.f);
            const ulonglong2* w0p = (const ulonglong2*)&ws[r0*WS1] + ks*36;
            const ulonglong2* w1p = (const ulonglong2*)&ws[(r0+1)*WS1] + ks*36;
            const ulonglong2* w2p = (const ulonglong2*)&ws[(r0+2)*WS1] + ks*36;
            const ulonglong2* w3p = (const ulonglong2*)&ws[(r0+3)*WS1] + ks*36;
            const ulonglong2* xp  = (const ulonglong2*)&xin[b*XS1] + ks*36;
            #pragma unroll 4
            for (int k4 = 0; k4 < 36; k4++){
                ulonglong2 xv = xp[k4];
                ulonglong2 wv0=w0p[k4], wv1=w1p[k4], wv2=w2p[k4], wv3=w3p[k4];
                ffma2(A0, wv0.x, xv.x); ffma2(A0, wv0.y, xv.y);
                ffma2(A1, wv1.x, xv.x); ffma2(A1, wv1.y, xv.y);
                ffma2(A2, wv2.x, xv.x); ffma2(A2, wv2.y, xv.y);
                ffma2(A3, wv3.x, xv.x); ffma2(A3, wv3.y, xv.y);
            }
            float* gb = ks ? gbuf2 : gbuf;
            gb[r0*17+b]     = red2(A0);
            gb[(r0+1)*17+b] = red2(A1);
            gb[(r0+2)*17+b] = red2(A2);
            gb[(r0+3)*17+b] = red2(A3);
        }
        __syncthreads();
        if (tid < 256){
            int uu = tid&15, bb = tid>>4;
            float gi=gbuf[uu*17+bb]      + gbuf2[uu*17+bb];
            float gf=gbuf[(16+uu)*17+bb] + gbuf2[(16+uu)*17+bb];
            float gg=gbuf[(32+uu)*17+bb] + gbuf2[(32+uu)*17+bb];
            float go=gbuf[(48+uu)*17+bb] + gbuf2[(48+uu)*17+bb];
            float cold = cs[tid];
            float cnew = sigm(gf)*cold + sigm(gi)*tanhf(gg);
            float hnew = sigm(go)*tanhf(cnew);
            cs[tid] = cnew;
            __stcg(&g_h1p[t&1][d*B_*HID+(b0+bb)*HID+u0+uu], hnew);
            int tt = d ? (TDEC-1-t) : t;
            g_d2in[((b0+bb)*TDEC+tt)*512 + d*HID + u0 + uu] = hnew;
        }
        bt += NBLK; gridbar(&g_bc1, bt);
    }
}

// ---------- dec2 persistent: 512 threads, K-split ----------
#define D2P_FL (64*WS2+16*XS2+1088+1088+256)
#define D2P_SMEM (D2P_FL*4)
__global__ void __launch_bounds__(512,1) dec2_persist(const float* __restrict__ whh,
        const float* __restrict__ ig, float* __restrict__ outbuf, unsigned* ctr){
    extern __shared__ __align__(16) float sm[];
    float* ws    = sm;
    float* hb    = ws + 64*WS2;
    float* gbuf  = hb + 16*XS2;
    float* gbuf2 = gbuf + 1088;
    float* cs    = gbuf2 + 1088;
    int tid = threadIdx.x, bid = blockIdx.x;
    int u0 = (bid & 15)*16, bg = (bid>>4)&3, d = bid>>6, b0 = bg*16;
    const float* whh_d = whh + d*G4*HID;
    const float* ig_d  = ig + (size_t)d*(B_*TDEC*G4);
    for (int i = tid; i < 64*256; i += 512){
        int r = i>>8, k = i&255;
        int gate = (r>>4)*HID + u0 + (r&15);
        ws[r*WS2+k] = whh_d[gate*HID+k];
    }
    if (tid < 256) cs[tid] = 0.f;
    __syncthreads();

    int ks = tid >> 8, rem = tid & 255;
    int b = rem & 15, rg = rem >> 4, r0 = rg*4;
    int gbase = (rg>>2)*HID + u0 + (rg&3)*4;

    unsigned bt = 0;
    for (int t = 0; t < TDEC; t++){
        int tt = d ? (TDEC-1-t) : t;
        const float* hprev = g_h2p[(t+1)&1];
        for (int i = tid; i < 16*256; i += 512){
            int bb = i>>8, k = i&255;
            hb[bb*XS2 + k] = (t > 0) ? __ldcg(&hprev[d*B_*HID+(b0+bb)*HID+k]) : 0.f;
        }
        __syncthreads();
        unsigned long long A0, A1, A2, A3;
        if (ks == 0){
            float4 ig4 = *(const float4*)&ig_d[((size_t)(b0+b)*TDEC+tt)*G4 + gbase];
            A0 = pk2(ig4.x, 0.f); A1 = pk2(ig4.y, 0.f);
            A2 = pk2(ig4.z, 0.f); A3 = pk2(ig4.w, 0.f);
        } else {
            A0 = pk2(0.f,0.f); A1 = A0; A2 = A0; A3 = A0;
        }
        const ulonglong2* w0p = (const ulonglong2*)&ws[r0*WS2] + ks*32;
        const ulonglong2* w1p = (const ulonglong2*)&ws[(r0+1)*WS2] + ks*32;
        const ulonglong2* w2p = (const ulonglong2*)&ws[(r0+2)*WS2] + ks*32;
        const ulonglong2* w3p = (const ulonglong2*)&ws[(r0+3)*WS2] + ks*32;
        const ulonglong2* xp  = (const ulonglong2*)&hb[b*XS2] + ks*32;
        #pragma unroll 8
        for (int k4 = 0; k4 < 32; k4++){
            ulonglong2 xv = xp[k4];
            ulonglong2 wv0=w0p[k4], wv1=w1p[k4], wv2=w2p[k4], wv3=w3p[k4];
            ffma2(A0, wv0.x, xv.x); ffma2(A0, wv0.y, xv.y);
            ffma2(A1, wv1.x, xv.x); ffma2(A1, wv1.y, xv.y);
            ffma2(A2, wv2.x, xv.x); ffma2(A2, wv2.y, xv.y);
            ffma2(A3, wv3.x, xv.x); ffma2(A3, wv3.y, xv.y);
        }
        float* gb = ks ? gbuf2 : gbuf;
        gb[r0*17+b]     = red2(A0);
        gb[(r0+1)*17+b] = red2(A1);
        gb[(r0+2)*17+b] = red2(A2);
        gb[(r0+3)*17+b] = red2(A3);
        __syncthreads();
        if (tid < 256){
            int uu = tid&15, bb = tid>>4;
            float gi=gbuf[uu*17+bb]      + gbuf2[uu*17+bb];
            float gf=gbuf[(16+uu)*17+bb] + gbuf2[(16+uu)*17+bb];
            float gg=gbuf[(32+uu)*17+bb] + gbuf2[(32+uu)*17+bb];
            float go=gbuf[(48+uu)*17+bb] + gbuf2[(48+uu)*17+bb];
            float cold = cs[tid];
            float cnew = sigm(gf)*cold + sigm(gi)*tanhf(gg);
            float hnew = sigm(go)*tanhf(cnew);
            cs[tid] = cnew;
            __stcg(&g_h2p[t&1][d*B_*HID+(b0+bb)*HID+u0+uu], hnew);
            outbuf[((b0+bb)*TDEC+tt)*512 + d*HID + u0 + uu] = hnew;
        }
        bt += NBLK; gridbar(ctr, bt);
    }
}

// ---------- GEMM ----------
__global__ void __launch_bounds__(256) gemm_tn(const float* __restrict__ A,
        const float* __restrict__ W, const float* __restrict__ b1,
        const float* __restrict__ b2, float* __restrict__ C, int K, int ldc){
    __shared__ __align__(16) float As[16][68];
    __shared__ __align__(16) float Ws[16][68];
    int bm = blockIdx.x*64, bn = blockIdx.y*64;
    int tid = threadIdx.x, tx = tid&15, ty = tid>>4;
    unsigned long long acc[4][2];
    #pragma unroll
    for (int i = 0; i < 4; i++){ acc[i][0]=pk2(0.f,0.f); acc[i][1]=acc[i][0]; }
    for (int k0 = 0; k0 < K; k0 += 16){
        #pragma unroll
        for (int i = tid; i < 1024; i += 256){
            int r = i>>4, c = i&15;
            As[c][r] = A[(size_t)(bm+r)*K + k0 + c];
            Ws[c][r] = W[(size_t)(bn+r)*K + k0 + c];
        }
        __syncthreads();
        #pragma unroll
        for (int k = 0; k < 16; k++){
            float4 av = *(const float4*)&As[k][ty*4];
            float4 wv = *(const float4*)&Ws[k][tx*4];
            unsigned long long w01 = pk2(wv.x, wv.y), w23 = pk2(wv.z, wv.w);
            float aa[4] = {av.x, av.y, av.z, av.w};
            #pragma unroll
            for (int i = 0; i < 4; i++){
                unsigned long long ad = pk2(aa[i], aa[i]);
                ffma2(acc[i][0], ad, w01);
                ffma2(acc[i][1], ad, w23);
            }
        }
        __syncthreads();
    }
    #pragma unroll
    for (int i = 0; i < 4; i++){
        float c0,c1,c2,c3;
        upk2(acc[i][0], c0, c1); upk2(acc[i][1], c2, c3);
        int row = bm + ty*4 + i, col = bn + tx*4;
        float r[4] = {c0,c1,c2,c3};
        #pragma unroll
        for (int j = 0; j < 4; j++){
            float bb = b1[col+j] + (b2 ? b2[col+j] : 0.f);
            C[(size_t)row*ldc + col + j] = r[j] + bb;
        }
    }
}

extern "C" void kernel_launch(void* const* d_in, const int* in_sizes, int n_in,
                              void* d_out, int out_size){
    const float* x       = (const float*)d_in[0];
    const float* conv_w1 = (const float*)d_in[1];
    const float* conv_b1 = (const float*)d_in[2];
    const float* conv_w2 = (const float*)d_in[3];
    const float* conv_b2 = (const float*)d_in[4];
    const float* conv_w3 = (const float*)d_in[5];
    const float* conv_b3 = (const float*)d_in[6];
    const float* attn_w  = (const float*)d_in[7];
    const float* dec1_wih = (const float*)d_in[9];
    const float* dec1_whh = (const float*)d_in[10];
    const float* dec1_bih = (const float*)d_in[11];
    const float* dec1_bhh = (const float*)d_in[12];
    const float* dec2_wih0 = (const float*)d_in[13];
    const float* dec2_whh0 = (const float*)d_in[14];
    const float* dec2_bih0 = (const float*)d_in[15];
    const float* dec2_bhh0 = (const float*)d_in[16];
    const float* dec2_wih1 = (const float*)d_in[17];
    const float* dec2_whh1 = (const float*)d_in[18];
    const float* dec2_bih1 = (const float*)d_in[19];
    const float* dec2_bhh1 = (const float*)d_in[20];
    const float* out_w = (const float*)d_in[21];
    const float* out_b = (const float*)d_in[22];
    float* out = (float*)d_out;

    cudaFuncSetAttribute(dec1_persist, cudaFuncAttributeMaxDynamicSharedMemorySize, D1P_SMEM);
    cudaFuncSetAttribute(dec2_persist, cudaFuncAttributeMaxDynamicSharedMemorySize, D2P_SMEM);

    float *p_d2in, *p_ig, *p_l0, *p_l1;
    unsigned *p_bc2a, *p_bc2b;
    cudaGetSymbolAddress((void**)&p_d2in, g_d2in);
    cudaGetSymbolAddress((void**)&p_ig,   g_ig);
    cudaGetSymbolAddress((void**)&p_l0,   g_l0);
    cudaGetSymbolAddress((void**)&p_l1,   g_l1);
    cudaGetSymbolAddress((void**)&p_bc2a, g_bc2a);
    cudaGetSymbolAddress((void**)&p_bc2b, g_bc2b);

    conv1_kernel<<<dim3(32, B_), 256>>>(x, conv_w1, conv_b1);
    conv2_kernel<<<dim3(16, B_), 256>>>(conv_w2, conv_b2);
    conv3_kernel<<<dim3(32, B_), 256>>>(conv_w3, conv_b3);

    dec1_persist<<<NBLK, 512, D1P_SMEM>>>(attn_w, dec1_wih, dec1_whh, dec1_bih, dec1_bhh);

    for (int d = 0; d < 2; d++)
        gemm_tn<<<dim3(60, 16), 256>>>(p_d2in, dec2_wih0 + d*G4*512,
            dec2_bih0 + d*G4, dec2_bhh0 + d*G4, p_ig + (size_t)d*B_*TDEC*G4, 512, G4);
    dec2_persist<<<NBLK, 512, D2P_SMEM>>>(dec2_whh0, p_ig, p_l0, p_bc2a);

    for (int d = 0; d < 2; d++)
        gemm_tn<<<dim3(60, 16), 256>>>(p_l0, dec2_wih1 + d*G4*512,
            dec2_bih1 + d*G4, dec2_bhh1 + d*G4, p_ig + (size_t)d*B_*TDEC*G4, 512, G4);
    dec2_persist<<<NBLK, 512, D2P_SMEM>>>(dec2_whh1, p_ig, p_l1, p_bc2b);

    gemm_tn<<<dim3(60, 2), 256>>>(p_l1, out_w, out_b, (const float*)nullptr, out, 512, 128);
}

// round 16
// speedup vs baseline: 1.5781x; 1.5781x over previous
#include <cuda_runtime.h>
#include <math.h>

#define B_    64
#define L_    4096
#define DIN   64
#define L1C   4093
#define L2C   4086
#define L3C   4071
#define HID   256
#define G4    1024
#define TDEC  60
#define CH    2036
#define NBLK  128u
#define WS1   292
#define XS1   292
#define WS2   260
#define XS2   260

__device__ float g_y1 [B_*L1C*8];
__device__ float g_y2 [B_*L2C*16];
__device__ float g_enc[B_*L3C*32];
__device__ float g_h1p[2][2*B_*HID];
__device__ float g_part[2*64*2*34];
__device__ float g_d2in[B_*TDEC*512];
__device__ float g_ig [2*B_*TDEC*G4];
__device__ float g_h2p[2][2*B_*HID];
__device__ float g_l0 [B_*TDEC*512];
__device__ float g_l1 [B_*TDEC*512];
__device__ unsigned g_bc1, g_bc2a, g_bc2b;

__device__ __forceinline__ void gridbar(unsigned* ctr, unsigned target){
    __syncthreads();
    if (threadIdx.x == 0){
        asm volatile("red.release.gpu.global.add.u32 [%0], 1;" :: "l"(ctr) : "memory");
        unsigned v;
        do { asm volatile("ld.acquire.gpu.global.u32 %0, [%1];" : "=r"(v) : "l"(ctr) : "memory"); } while (v < target);
    }
    __syncthreads();
}

__device__ __forceinline__ float sigm(float x){ return 1.f/(1.f+__expf(-x)); }
__device__ __forceinline__ unsigned long long pk2(float x, float y){
    unsigned long long r; asm("mov.b64 %0, {%1, %2};" : "=l"(r) : "f"(x), "f"(y)); return r;
}
__device__ __forceinline__ void upk2(unsigned long long v, float &x, float &y){
    asm("mov.b64 {%0, %1}, %2;" : "=f"(x), "=f"(y) : "l"(v));
}
__device__ __forceinline__ void ffma2(unsigned long long &c, unsigned long long a, unsigned long long b){
    asm("fma.rn.f32x2 %0, %1, %2, %0;" : "+l"(c) : "l"(a), "l"(b));
}
__device__ __forceinline__ unsigned long long mul2(unsigned long long a, unsigned long long b){
    unsigned long long r; asm("mul.rn.f32x2 %0, %1, %2;" : "=l"(r) : "l"(a), "l"(b)); return r;
}
__device__ __forceinline__ float red2(unsigned long long v){
    float lo, hi; upk2(v, lo, hi); return lo + hi;
}

// ---------- conv1 ----------
__global__ void __launch_bounds__(256) conv1_kernel(const float* __restrict__ x,
        const float* __restrict__ w, const float* __restrict__ bias){
    if (blockIdx.x == 0 && blockIdx.y == 0 && threadIdx.x == 0){
        g_bc1 = 0u; g_bc2a = 0u; g_bc2b = 0u;
    }
    __shared__ __align__(16) float xs[131*68];
    __shared__ __align__(16) float ws[32*68];
    int b = blockIdx.y, l0 = blockIdx.x*128, tid = threadIdx.x;
    for (int i = tid; i < 2048; i += 256){
        int o = i>>8, ii = (i>>2)&63, t = i&3;
        ws[(t*8+o)*68+ii] = w[i];
    }
    for (int i = tid; i < 131*64; i += 256){
        int p = i>>6, c = i&63, l = l0+p;
        xs[p*68+c] = (l < L_) ? x[(b*L_+l)*DIN+c] : 0.f;
    }
    __syncthreads();
    for (int oi = 0; oi < 4; oi++){
        int idx = tid + oi*256;
        int l = idx>>3, o = idx&7, gl = l0+l;
        if (gl >= L1C) continue;
        unsigned long long acc = pk2(bias[o], 0.f);
        #pragma unroll
        for (int t = 0; t < 4; t++){
            const ulonglong2* xp = (const ulonglong2*)&xs[(l+t)*68];
            const ulonglong2* wp = (const ulonglong2*)&ws[(t*8+o)*68];
            #pragma unroll
            for (int q = 0; q < 16; q++){
                ulonglong2 xv = xp[q], wv = wp[q];
                ffma2(acc, wv.x, xv.x);
                ffma2(acc, wv.y, xv.y);
            }
        }
        g_y1[(b*L1C+gl)*8+o] = fmaxf(red2(acc), 0.f);
    }
}

// ---------- conv2 ----------
__global__ void __launch_bounds__(256) conv2_kernel(const float* __restrict__ w,
        const float* __restrict__ bias){
    __shared__ __align__(16) float xs[263*8];
    __shared__ __align__(16) float ws[128*12];
    int b = blockIdx.y, l0 = blockIdx.x*256, tid = threadIdx.x;
    for (int i = tid; i < 1024; i += 256){
        int o = i>>6, ii = (i>>3)&7, t = i&7;
        ws[(t*16+o)*12+ii] = w[i];
    }
    for (int i = tid; i < 263*8; i += 256){
        int p = i>>3, c = i&7, l = l0+p;
        xs[i] = (l < L1C) ? g_y1[(b*L1C+l)*8+c] : 0.f;
    }
    __syncthreads();
    for (int oi = 0; oi < 16; oi++){
        int idx = tid + oi*256;
        int l = idx>>4, o = idx&15, gl = l0+l;
        if (gl >= L2C) continue;
        unsigned long long acc = pk2(bias[o], 0.f);
        #pragma unroll
        for (int t = 0; t < 8; t++){
            const ulonglong2* xp = (const ulonglong2*)&xs[(l+t)*8];
            const ulonglong2* wp = (const ulonglong2*)&ws[(t*16+o)*12];
            ulonglong2 x0 = xp[0], x1 = xp[1], w0 = wp[0], w1 = wp[1];
            ffma2(acc, w0.x, x0.x); ffma2(acc, w0.y, x0.y);
            ffma2(acc, w1.x, x1.x); ffma2(acc, w1.y, x1.y);
        }
        g_y2[(b*L2C+gl)*16+o] = fmaxf(red2(acc), 0.f);
    }
}

// ---------- conv3 ----------
__global__ void __launch_bounds__(256) conv3_kernel(const float* __restrict__ w,
        const float* __restrict__ bias){
    __shared__ __align__(16) float xs[143*20+4];
    __shared__ __align__(16) float4 ws4[64*32];
    __shared__ float bsm[32];
    int b = blockIdx.y, l0 = blockIdx.x*128, tid = threadIdx.x;
    for (int i = tid; i < 2048; i += 256){
        int o = i >> 6, tq = i & 63, t = tq >> 2, q = tq & 3;
        float4 v;
        v.x = w[o*256 + (q*4+0)*16 + t];
        v.y = w[o*256 + (q*4+1)*16 + t];
        v.z = w[o*256 + (q*4+2)*16 + t];
        v.w = w[o*256 + (q*4+3)*16 + t];
        ws4[tq*32 + o] = v;
    }
    for (int i = tid; i < 143*16; i += 256){
        int p = i >> 4, c = i & 15, l = l0 + p;
        xs[p*20 + c] = (l < L2C) ? g_y2[(b*L2C+l)*16+c] : 0.f;
    }
    if (tid < 32) bsm[tid] = bias[tid];
    __syncthreads();
    int og = tid & 7, lg = tid >> 3;
    unsigned long long acc[4][4];
    #pragma unroll
    for (int i = 0; i < 4; i++)
        #pragma unroll
        for (int j = 0; j < 4; j++) acc[i][j] = pk2(0.f, 0.f);
    for (int t = 0; t < 16; t++){
        #pragma unroll
        for (int q = 0; q < 4; q++){
            int tq = t*4+q;
            ulonglong2 wv[4], xv[4];
            #pragma unroll
            for (int i = 0; i < 4; i++) wv[i] = *(const ulonglong2*)&ws4[tq*32 + og + i*8];
            #pragma unroll
            for (int j = 0; j < 4; j++) xv[j] = *(const ulonglong2*)&xs[(lg + 32*j + t)*20 + q*4];
            #pragma unroll
            for (int i = 0; i < 4; i++)
                #pragma unroll
                for (int j = 0; j < 4; j++){
                    ffma2(acc[i][j], wv[i].x, xv[j].x);
                    ffma2(acc[i][j], wv[i].y, xv[j].y);
                }
        }
    }
    #pragma unroll
    for (int i = 0; i < 4; i++){
        int o = og + i*8;
        #pragma unroll
        for (int j = 0; j < 4; j++){
            int gl = l0 + lg + 32*j;
            if (gl < L3C)
                g_enc[((size_t)b*L3C+gl)*32+o] = fmaxf(red2(acc[i][j]) + bsm[o], 0.f);
        }
    }
}

// ---------- dec1 persistent: 512 threads ----------
#define D1P_FL (64*WS1+8192+16*XS1+1088+1088+64+256+64)
#define D1P_SMEM (D1P_FL*4)
__global__ void __launch_bounds__(512,1) dec1_persist(const float* __restrict__ attn_w,
        const float* __restrict__ wih, const float* __restrict__ whh,
        const float* __restrict__ bih, const float* __restrict__ bhh){
    extern __shared__ __align__(16) float sm[];
    float* ws   = sm;
    float* aw   = ws + 64*WS1;
    float* xin  = aw + 8192;
    float* gbuf = xin + 16*XS1;
    float* wred = gbuf + 1088;
    float* us   = wred + 1088;
    float* cs   = us + 64;
    float* bs   = cs + 256;
    int tid = threadIdx.x, bid = blockIdx.x;
    int ab = bid >> 1, ah = bid & 1;
    int u0 = (bid & 15)*16, bg = (bid>>4)&3, d = bid>>6, b0 = bg*16;

    const float* wih_d = wih + d*G4*32;
    const float* whh_d = whh + d*G4*HID;
    for (int i = tid; i < 64*288; i += 512){
        int r = i/288, k = i-r*288;
        int gate = (r>>4)*HID + u0 + (r&15);
        ws[r*WS1+k] = (k < 32) ? wih_d[gate*32+k] : whh_d[gate*HID+k-32];
    }
    for (int i = tid; i < 8192; i += 512) aw[i] = attn_w[i];
    if (tid < 64){
        int gate = (tid>>4)*HID + u0 + (tid&15);
        bs[tid] = bih[d*G4+gate] + bhh[d*G4+gate];
    }
    if (tid < 256) cs[tid] = 0.f;
    __syncthreads();

    unsigned bt = 0;
    const float* encb = g_enc + (size_t)ab*(L3C*32);
    int lo = ah*CH, hi = (lo+CH < L3C) ? lo+CH : L3C;
    int chh = tid & 1, lslice = tid >> 1;

    for (int t = 0; t < TDEC; t++){
        const float* hprev = g_h1p[(t+1)&1];
        {
            int dd = tid>>8, rem = tid&255, c = rem&31, kp = rem>>5;
            float acc = 0.f;
            if (t > 0){
                const float4* h4 = (const float4*)(hprev + dd*B_*HID + ab*HID + kp*32);
                const float* awp = aw + kp*32*32 + c;
                #pragma unroll
                for (int k = 0; k < 8; k++){
                    float4 hv = __ldcg(&h4[k]);
                    acc += hv.x*awp[(k*4+0)*32] + hv.y*awp[(k*4+1)*32]
                         + hv.z*awp[(k*4+2)*32] + hv.w*awp[(k*4+3)*32];
                }
            }
            gbuf[tid] = acc;
        }
        __syncthreads();
        if (tid < 64){
            int dd = tid>>5, c = tid&31;
            float s = 0.f;
            #pragma unroll
            for (int j = 0; j < 8; j++) s += gbuf[dd*256 + j*32 + c];
            us[tid] = s;
        }
        __syncthreads();
        unsigned long long uf[8], ub[8];
        {
            const unsigned long long* ufp = (const unsigned long long*)&us[chh*16];
            const unsigned long long* ubp = (const unsigned long long*)&us[32 + chh*16];
            #pragma unroll
            for (int i = 0; i < 8; i++){ uf[i] = ufp[i]; ub[i] = ubp[i]; }
        }
        float mf = -1e30f, mb = -1e30f, sf = 0.f, sb = 0.f;
        unsigned long long vf2[8], vb2[8];
        #pragma unroll
        for (int i = 0; i < 8; i++){ vf2[i] = pk2(0.f,0.f); vb2[i] = vf2[i]; }
        #pragma unroll 2
        for (int it = 0; it < 8; it++){
            int l = lo + lslice + it*256;
            bool valid = (l < hi);
            ulonglong2 ev2[4];
            if (valid){
                const ulonglong2* e2 = (const ulonglong2*)(encb + l*32 + chh*16);
                #pragma unroll
                for (int j = 0; j < 4; j++) ev2[j] = e2[j];
            } else {
                #pragma unroll
                for (int j = 0; j < 4; j++){ ev2[j].x = 0ull; ev2[j].y = 0ull; }
            }
            unsigned long long dA = pk2(0.f,0.f), dB = dA;
            #pragma unroll
            for (int j = 0; j < 4; j++){
                ffma2(dA, ev2[j].x, uf[2*j]);   ffma2(dA, ev2[j].y, uf[2*j+1]);
                ffma2(dB, ev2[j].x, ub[2*j]);   ffma2(dB, ev2[j].y, ub[2*j+1]);
            }
            float df = red2(dA); df += __shfl_xor_sync(0xffffffffu, df, 1);
            float db = red2(dB); db += __shfl_xor_sync(0xffffffffu, db, 1);
            if (!valid){ df = -1e30f; db = -1e30f; }
            if (df > mf){
                float sc = __expf(mf-df); sf *= sc;
                unsigned long long sc2 = pk2(sc,sc);
                #pragma unroll
                for (int i = 0; i < 8; i++) vf2[i] = mul2(vf2[i], sc2);
                mf = df;
            }
            float pf = __expf(df-mf); sf += pf;
            unsigned long long pf2 = pk2(pf,pf);
            #pragma unroll
            for (int j = 0; j < 4; j++){
                ffma2(vf2[2*j],   pf2, ev2[j].x);
                ffma2(vf2[2*j+1], pf2, ev2[j].y);
            }
            if (db > mb){
                float sc = __expf(mb-db); sb *= sc;
                unsigned long long sc2 = pk2(sc,sc);
                #pragma unroll
                for (int i = 0; i < 8; i++) vb2[i] = mul2(vb2[i], sc2);
                mb = db;
            }
            float pb = __expf(db-mb); sb += pb;
            unsigned long long pb2 = pk2(pb,pb);
            #pragma unroll
            for (int j = 0; j < 4; j++){
                ffma2(vb2[2*j],   pb2, ev2[j].x);
                ffma2(vb2[2*j+1], pb2, ev2[j].y);
            }
        }
        #pragma unroll
        for (int off = 2; off <= 16; off <<= 1){
            float mo = __shfl_xor_sync(0xffffffffu, mf, off);
            float so = __shfl_xor_sync(0xffffffffu, sf, off);
            float M = fmaxf(mf, mo); float ea=__expf(mf-M), eb=__expf(mo-M);
            unsigned long long ea2 = pk2(ea,ea), eb2 = pk2(eb,eb);
            sf = sf*ea + so*eb;
            #pragma unroll
            for (int i = 0; i < 8; i++){
                unsigned long long vo = __shfl_xor_sync(0xffffffffu, vf2[i], off);
                vf2[i] = mul2(vf2[i], ea2); ffma2(vf2[i], eb2, vo);
            }
            mf = M;
            mo = __shfl_xor_sync(0xffffffffu, mb, off);
            so = __shfl_xor_sync(0xffffffffu, sb, off);
            M = fmaxf(mb, mo); ea=__expf(mb-M); eb=__expf(mo-M);
            ea2 = pk2(ea,ea); eb2 = pk2(eb,eb);
            sb = sb*ea + so*eb;
            #pragma unroll
            for (int i = 0; i < 8; i++){
                unsigned long long vo = __shfl_xor_sync(0xffffffffu, vb2[i], off);
                vb2[i] = mul2(vb2[i], ea2); ffma2(vb2[i], eb2, vo);
            }
            mb = M;
        }
        {
            int lane = tid & 31, wq = tid >> 5;
            float* p = wred + wq*68;
            if (lane < 2){
                if (lane == 0){ p[0]=mf; p[1]=sf; p[34]=mb; p[35]=sb; }
                float* v0 = p + 2 + chh*16;
                float* v1 = p + 36 + chh*16;
                #pragma unroll
                for (int i = 0; i < 8; i++){
                    float lo2, hi2;
                    upk2(vf2[i], lo2, hi2); v0[i*2]=lo2; v0[i*2+1]=hi2;
                    upk2(vb2[i], lo2, hi2); v1[i*2]=lo2; v1[i*2+1]=hi2;
                }
            }
        }
        __syncthreads();
        if (tid < 32){
            #pragma unroll
            for (int dir = 0; dir < 2; dir++){
                float M=-1e30f, S=0.f, V=0.f;
                #pragma unroll
                for (int j = 0; j < 16; j++){
                    const float* p = wred + j*68 + dir*34;
                    float mj=p[0], sj=p[1], vj=p[2+tid];
                    float nM=fmaxf(M,mj); float ea=__expf(M-nM), eb=__expf(mj-nM);
                    V=V*ea+vj*eb; S=S*ea+sj*eb; M=nM;
                }
                int pb2i = ((dir*64+ab)*2+ah)*34;
                __stcg(&g_part[pb2i+2+tid], V);
                if (tid == 0){ __stcg(&g_part[pb2i], M); __stcg(&g_part[pb2i+1], S); }
            }
        }
        bt += NBLK; gridbar(&g_bc1, bt);

        for (int i = tid; i < 16*288; i += 512){
            int bb = i/288, k = i-bb*288; float v;
            if (k < 32){
                int b = b0+bb;
                const float* p0 = &g_part[((d*64+b)*2+0)*34];
                const float* p1 = p0 + 34;
                float m0=__ldcg(p0), s0=__ldcg(p0+1), v0=__ldcg(p0+2+k);
                float m1=__ldcg(p1), s1=__ldcg(p1+1), v1=__ldcg(p1+2+k);
                float M=fmaxf(m0,m1); float e0=__expf(m0-M), e1=__expf(m1-M);
                v = (v0*e0+v1*e1)/(s0*e0+s1*e1);
            } else {
                v = (t > 0) ? __ldcg(&hprev[d*B_*HID+(b0+bb)*HID+k-32]) : 0.f;
            }
            xin[bb*XS1 + k] = v;
        }
        __syncthreads();
        if (tid < 256){
            int b = tid & 15, rg = tid >> 4, r0 = rg*4;
            unsigned long long A0 = pk2(bs[r0],   0.f);
            unsigned long long A1 = pk2(bs[r0+1], 0.f);
            unsigned long long A2 = pk2(bs[r0+2], 0.f);
            unsigned long long A3 = pk2(bs[r0+3], 0.f);
            const ulonglong2* w0p = (const ulonglong2*)&ws[r0*WS1];
            const ulonglong2* w1p = (const ulonglong2*)&ws[(r0+1)*WS1];
            const ulonglong2* w2p = (const ulonglong2*)&ws[(r0+2)*WS1];
            const ulonglong2* w3p = (const ulonglong2*)&ws[(r0+3)*WS1];
            const ulonglong2* xp  = (const ulonglong2*)&xin[b*XS1];
            #pragma unroll 8
            for (int k4 = 0; k4 < 72; k4++){
                ulonglong2 xv = xp[k4];
                ulonglong2 wv0=w0p[k4], wv1=w1p[k4], wv2=w2p[k4], wv3=w3p[k4];
                ffma2(A0, wv0.x, xv.x); ffma2(A0, wv0.y, xv.y);
                ffma2(A1, wv1.x, xv.x); ffma2(A1, wv1.y, xv.y);
                ffma2(A2, wv2.x, xv.x); ffma2(A2, wv2.y, xv.y);
                ffma2(A3, wv3.x, xv.x); ffma2(A3, wv3.y, xv.y);
            }
            gbuf[r0*17+b]     = red2(A0);
            gbuf[(r0+1)*17+b] = red2(A1);
            gbuf[(r0+2)*17+b] = red2(A2);
            gbuf[(r0+3)*17+b] = red2(A3);
        }
        __syncthreads();
        if (tid < 256){
            int uu = tid&15, bb = tid>>4;
            float gi=gbuf[uu*17+bb], gf=gbuf[(16+uu)*17+bb];
            float gg=gbuf[(32+uu)*17+bb], go=gbuf[(48+uu)*17+bb];
            float cold = cs[tid];
            float cnew = sigm(gf)*cold + sigm(gi)*tanhf(gg);
            float hnew = sigm(go)*tanhf(cnew);
            cs[tid] = cnew;
            __stcg(&g_h1p[t&1][d*B_*HID+(b0+bb)*HID+u0+uu], hnew);
            int tt = d ? (TDEC-1-t) : t;
            g_d2in[((b0+bb)*TDEC+tt)*512 + d*HID + u0 + uu] = hnew;
        }
        bt += NBLK; gridbar(&g_bc1, bt);
    }
}

// ---------- dec2 persistent ----------
#define D2P_FL (64*WS2+16*XS2+1088+256)
#define D2P_SMEM (D2P_FL*4)
__global__ void __launch_bounds__(256,1) dec2_persist(const float* __restrict__ whh,
        const float* __restrict__ ig, float* __restrict__ outbuf, unsigned* ctr){
    extern __shared__ __align__(16) float sm[];
    float* ws   = sm;
    float* hb   = ws + 64*WS2;
    float* gbuf = hb + 16*XS2;
    float* cs   = gbuf + 1088;
    int tid = threadIdx.x, bid = blockIdx.x;
    int u0 = (bid & 15)*16, bg = (bid>>4)&3, d = bid>>6, b0 = bg*16;
    const float* whh_d = whh + d*G4*HID;
    const float* ig_d  = ig + (size_t)d*(B_*TDEC*G4);
    for (int i = tid; i < 64*256; i += 256){
        int r = i>>8, k = i&255;
        int gate = (r>>4)*HID + u0 + (r&15);
        ws[r*WS2+k] = whh_d[gate*HID+k];
    }
    cs[tid] = 0.f;
    __syncthreads();

    int b = tid & 15, rg = tid >> 4, r0 = rg*4;
    int gbase = (rg>>2)*HID + u0 + (rg&3)*4;

    unsigned bt = 0;
    for (int t = 0; t < TDEC; t++){
        int tt = d ? (TDEC-1-t) : t;
        const float* hprev = g_h2p[(t+1)&1];
        for (int i = tid; i < 16*64; i += 256){
            int bb = i>>6, k4 = i&63;
            float4 v;
            if (t > 0) v = __ldcg((const float4*)&hprev[d*B_*HID+(b0+bb)*HID+k4*4]);
            else       v = make_float4(0.f,0.f,0.f,0.f);
            *(float4*)&hb[bb*XS2 + k4*4] = v;
        }
        __syncthreads();
        float4 ig4 = *(const float4*)&ig_d[((size_t)(b0+b)*TDEC+tt)*G4 + gbase];
        unsigned long long A0 = pk2(ig4.x, 0.f);
        unsigned long long A1 = pk2(ig4.y, 0.f);
        unsigned long long A2 = pk2(ig4.z, 0.f);
        unsigned long long A3 = pk2(ig4.w, 0.f);
        const ulonglong2* w0p = (const ulonglong2*)&ws[r0*WS2];
        const ulonglong2* w1p = (const ulonglong2*)&ws[(r0+1)*WS2];
        const ulonglong2* w2p = (const ulonglong2*)&ws[(r0+2)*WS2];
        const ulonglong2* w3p = (const ulonglong2*)&ws[(r0+3)*WS2];
        const ulonglong2* xp  = (const ulonglong2*)&hb[b*XS2];
        #pragma unroll 8
        for (int k4 = 0; k4 < 64; k4++){
            ulonglong2 xv = xp[k4];
            ulonglong2 wv0=w0p[k4], wv1=w1p[k4], wv2=w2p[k4], wv3=w3p[k4];
            ffma2(A0, wv0.x, xv.x); ffma2(A0, wv0.y, xv.y);
            ffma2(A1, wv1.x, xv.x); ffma2(A1, wv1.y, xv.y);
            ffma2(A2, wv2.x, xv.x); ffma2(A2, wv2.y, xv.y);
            ffma2(A3, wv3.x, xv.x); ffma2(A3, wv3.y, xv.y);
        }
        gbuf[r0*17+b]     = red2(A0);
        gbuf[(r0+1)*17+b] = red2(A1);
        gbuf[(r0+2)*17+b] = red2(A2);
        gbuf[(r0+3)*17+b] = red2(A3);
        __syncthreads();
        {
            int uu = tid&15, bb = tid>>4;
            float gi=gbuf[uu*17+bb], gf=gbuf[(16+uu)*17+bb];
            float gg=gbuf[(32+uu)*17+bb], go=gbuf[(48+uu)*17+bb];
            float cold = cs[tid];
            float cnew = sigm(gf)*cold + sigm(gi)*tanhf(gg);
            float hnew = sigm(go)*tanhf(cnew);
            cs[tid] = cnew;
            __stcg(&g_h2p[t&1][d*B_*HID+(b0+bb)*HID+u0+uu], hnew);
            outbuf[((b0+bb)*TDEC+tt)*512 + d*HID + u0 + uu] = hnew;
        }
        bt += NBLK; gridbar(ctr, bt);
    }
}

// ---------- GEMM: z-dim over directions ----------
__global__ void __launch_bounds__(256) gemm_tn(const float* __restrict__ A,
        const float* __restrict__ W, const float* __restrict__ b1,
        const float* __restrict__ b2, float* __restrict__ C, int K, int ldc,
        long wstr, long bstr, long cstr){
    int z = blockIdx.z;
    W  += (size_t)z * wstr;
    b1 += (size_t)z * bstr;
    if (b2) b2 += (size_t)z * bstr;
    C  += (size_t)z * cstr;
    __shared__ __align__(16) float As[16][68];
    __shared__ __align__(16) float Ws[16][68];
    int bm = blockIdx.x*64, bn = blockIdx.y*64;
    int tid = threadIdx.x, tx = tid&15, ty = tid>>4;
    unsigned long long acc[4][2];
    #pragma unroll
    for (int i = 0; i < 4; i++){ acc[i][0]=pk2(0.f,0.f); acc[i][1]=acc[i][0]; }
    for (int k0 = 0; k0 < K; k0 += 16){
        #pragma unroll
        for (int i = tid; i < 1024; i += 256){
            int r = i>>4, c = i&15;
            As[c][r] = A[(size_t)(bm+r)*K + k0 + c];
            Ws[c][r] = W[(size_t)(bn+r)*K + k0 + c];
        }
        __syncthreads();
        #pragma unroll
        for (int k = 0; k < 16; k++){
            float4 av = *(const float4*)&As[k][ty*4];
            float4 wv = *(const float4*)&Ws[k][tx*4];
            unsigned long long w01 = pk2(wv.x, wv.y), w23 = pk2(wv.z, wv.w);
            float aa[4] = {av.x, av.y, av.z, av.w};
            #pragma unroll
            for (int i = 0; i < 4; i++){
                unsigned long long ad = pk2(aa[i], aa[i]);
                ffma2(acc[i][0], ad, w01);
                ffma2(acc[i][1], ad, w23);
            }
        }
        __syncthreads();
    }
    #pragma unroll
    for (int i = 0; i < 4; i++){
        float c0,c1,c2,c3;
        upk2(acc[i][0], c0, c1); upk2(acc[i][1], c2, c3);
        int row = bm + ty*4 + i, col = bn + tx*4;
        float r[4] = {c0,c1,c2,c3};
        #pragma unroll
        for (int j = 0; j < 4; j++){
            float bb = b1[col+j] + (b2 ? b2[col+j] : 0.f);
            C[(size_t)row*ldc + col + j] = r[j] + bb;
        }
    }
}

extern "C" void kernel_launch(void* const* d_in, const int* in_sizes, int n_in,
                              void* d_out, int out_size){
    const float* x       = (const float*)d_in[0];
    const float* conv_w1 = (const float*)d_in[1];
    const float* conv_b1 = (const float*)d_in[2];
    const float* conv_w2 = (const float*)d_in[3];
    const float* conv_b2 = (const float*)d_in[4];
    const float* conv_w3 = (const float*)d_in[5];
    const float* conv_b3 = (const float*)d_in[6];
    const float* attn_w  = (const float*)d_in[7];
    const float* dec1_wih = (const float*)d_in[9];
    const float* dec1_whh = (const float*)d_in[10];
    const float* dec1_bih = (const float*)d_in[11];
    const float* dec1_bhh = (const float*)d_in[12];
    const float* dec2_wih0 = (const float*)d_in[13];
    const float* dec2_whh0 = (const float*)d_in[14];
    const float* dec2_bih0 = (const float*)d_in[15];
    const float* dec2_bhh0 = (const float*)d_in[16];
    const float* dec2_wih1 = (const float*)d_in[17];
    const float* dec2_whh1 = (const float*)d_in[18];
    const float* dec2_bih1 = (const float*)d_in[19];
    const float* dec2_bhh1 = (const float*)d_in[20];
    const float* out_w = (const float*)d_in[21];
    const float* out_b = (const float*)d_in[22];
    float* out = (float*)d_out;

    cudaFuncSetAttribute(dec1_persist, cudaFuncAttributeMaxDynamicSharedMemorySize, D1P_SMEM);
    cudaFuncSetAttribute(dec2_persist, cudaFuncAttributeMaxDynamicSharedMemorySize, D2P_SMEM);

    float *p_d2in, *p_ig, *p_l0, *p_l1;
    unsigned *p_bc2a, *p_bc2b;
    cudaGetSymbolAddress((void**)&p_d2in, g_d2in);
    cudaGetSymbolAddress((void**)&p_ig,   g_ig);
    cudaGetSymbolAddress((void**)&p_l0,   g_l0);
    cudaGetSymbolAddress((void**)&p_l1,   g_l1);
    cudaGetSymbolAddress((void**)&p_bc2a, g_bc2a);
    cudaGetSymbolAddress((void**)&p_bc2b, g_bc2b);

    conv1_kernel<<<dim3(32, B_), 256>>>(x, conv_w1, conv_b1);
    conv2_kernel<<<dim3(16, B_), 256>>>(conv_w2, conv_b2);
    conv3_kernel<<<dim3(32, B_), 256>>>(conv_w3, conv_b3);

    dec1_persist<<<NBLK, 512, D1P_SMEM>>>(attn_w, dec1_wih, dec1_whh, dec1_bih, dec1_bhh);

    gemm_tn<<<dim3(60, 16, 2), 256>>>(p_d2in, dec2_wih0, dec2_bih0, dec2_bhh0,
        p_ig, 512, G4, (long)G4*512, (long)G4, (long)B_*TDEC*G4);
    dec2_persist<<<NBLK, 256, D2P_SMEM>>>(dec2_whh0, p_ig, p_l0, p_bc2a);

    gemm_tn<<<dim3(60, 16, 2), 256>>>(p_l0, dec2_wih1, dec2_bih1, dec2_bhh1,
        p_ig, 512, G4, (long)G4*512, (long)G4, (long)B_*TDEC*G4);
    dec2_persist<<<NBLK, 256, D2P_SMEM>>>(dec2_whh1, p_ig, p_l1, p_bc2b);

    gemm_tn<<<dim3(60, 2, 1), 256>>>(p_l1, out_w, out_b, (const float*)nullptr,
        out, 512, 128, 0L, 0L, 0L);
}

// round 17
// speedup vs baseline: 1.6355x; 1.0363x over previous
#include <cuda_runtime.h>
#include <math.h>

#define B_    64
#define L_    4096
#define DIN   64
#define L1C   4093
#define L2C   4086
#define L3C   4071
#define HID   256
#define G4    1024
#define TDEC  60
#define CH    2036
#define NBLK  128u
#define WS1   292
#define XS1   292
#define WS2   260
#define XS2   260

__device__ float g_y1 [B_*L1C*8];
__device__ float g_y2 [B_*L2C*16];
__device__ float g_enc[B_*L3C*32];
__device__ float g_h1p[2][2*B_*HID];
__device__ float g_part[2*64*2*34];
__device__ float g_d2in[B_*TDEC*512];
__device__ float g_ig [2*B_*TDEC*G4];
__device__ float g_h2p[2][2*B_*HID];
__device__ float g_l0 [B_*TDEC*512];
__device__ float g_l1 [B_*TDEC*512];
__device__ unsigned g_bc1, g_bc2a, g_bc2b;

__device__ __forceinline__ void gridbar(unsigned* ctr, unsigned target){
    __syncthreads();
    if (threadIdx.x == 0){
        asm volatile("red.release.gpu.global.add.u32 [%0], 1;" :: "l"(ctr) : "memory");
        unsigned v;
        do { asm volatile("ld.acquire.gpu.global.u32 %0, [%1];" : "=r"(v) : "l"(ctr) : "memory"); } while (v < target);
    }
    __syncthreads();
}

__device__ __forceinline__ float sigm(float x){ return 1.f/(1.f+__expf(-x)); }
__device__ __forceinline__ unsigned long long pk2(float x, float y){
    unsigned long long r; asm("mov.b64 %0, {%1, %2};" : "=l"(r) : "f"(x), "f"(y)); return r;
}
__device__ __forceinline__ void upk2(unsigned long long v, float &x, float &y){
    asm("mov.b64 {%0, %1}, %2;" : "=f"(x), "=f"(y) : "l"(v));
}
__device__ __forceinline__ void ffma2(unsigned long long &c, unsigned long long a, unsigned long long b){
    asm("fma.rn.f32x2 %0, %1, %2, %0;" : "+l"(c) : "l"(a), "l"(b));
}
__device__ __forceinline__ unsigned long long mul2(unsigned long long a, unsigned long long b){
    unsigned long long r; asm("mul.rn.f32x2 %0, %1, %2;" : "=l"(r) : "l"(a), "l"(b)); return r;
}
__device__ __forceinline__ float red2(unsigned long long v){
    float lo, hi; upk2(v, lo, hi); return lo + hi;
}

// ---------- conv1 ----------
__global__ void __launch_bounds__(256) conv1_kernel(const float* __restrict__ x,
        const float* __restrict__ w, const float* __restrict__ bias){
    if (blockIdx.x == 0 && blockIdx.y == 0 && threadIdx.x == 0){
        g_bc1 = 0u; g_bc2a = 0u; g_bc2b = 0u;
    }
    __shared__ __align__(16) float xs[131*68];
    __shared__ __align__(16) float ws[32*68];
    int b = blockIdx.y, l0 = blockIdx.x*128, tid = threadIdx.x;
    for (int i = tid; i < 2048; i += 256){
        int o = i>>8, ii = (i>>2)&63, t = i&3;
        ws[(t*8+o)*68+ii] = w[i];
    }
    for (int i = tid; i < 131*64; i += 256){
        int p = i>>6, c = i&63, l = l0+p;
        xs[p*68+c] = (l < L_) ? x[(b*L_+l)*DIN+c] : 0.f;
    }
    __syncthreads();
    for (int oi = 0; oi < 4; oi++){
        int idx = tid + oi*256;
        int l = idx>>3, o = idx&7, gl = l0+l;
        if (gl >= L1C) continue;
        unsigned long long acc = pk2(bias[o], 0.f);
        #pragma unroll
        for (int t = 0; t < 4; t++){
            const ulonglong2* xp = (const ulonglong2*)&xs[(l+t)*68];
            const ulonglong2* wp = (const ulonglong2*)&ws[(t*8+o)*68];
            #pragma unroll
            for (int q = 0; q < 16; q++){
                ulonglong2 xv = xp[q], wv = wp[q];
                ffma2(acc, wv.x, xv.x);
                ffma2(acc, wv.y, xv.y);
            }
        }
        g_y1[(b*L1C+gl)*8+o] = fmaxf(red2(acc), 0.f);
    }
}

// ---------- conv2 ----------
__global__ void __launch_bounds__(256) conv2_kernel(const float* __restrict__ w,
        const float* __restrict__ bias){
    __shared__ __align__(16) float xs[263*8];
    __shared__ __align__(16) float ws[128*12];
    int b = blockIdx.y, l0 = blockIdx.x*256, tid = threadIdx.x;
    for (int i = tid; i < 1024; i += 256){
        int o = i>>6, ii = (i>>3)&7, t = i&7;
        ws[(t*16+o)*12+ii] = w[i];
    }
    for (int i = tid; i < 263*8; i += 256){
        int p = i>>3, c = i&7, l = l0+p;
        xs[i] = (l < L1C) ? g_y1[(b*L1C+l)*8+c] : 0.f;
    }
    __syncthreads();
    for (int oi = 0; oi < 16; oi++){
        int idx = tid + oi*256;
        int l = idx>>4, o = idx&15, gl = l0+l;
        if (gl >= L2C) continue;
        unsigned long long acc = pk2(bias[o], 0.f);
        #pragma unroll
        for (int t = 0; t < 8; t++){
            const ulonglong2* xp = (const ulonglong2*)&xs[(l+t)*8];
            const ulonglong2* wp = (const ulonglong2*)&ws[(t*16+o)*12];
            ulonglong2 x0 = xp[0], x1 = xp[1], w0 = wp[0], w1 = wp[1];
            ffma2(acc, w0.x, x0.x); ffma2(acc, w0.y, x0.y);
            ffma2(acc, w1.x, x1.x); ffma2(acc, w1.y, x1.y);
        }
        g_y2[(b*L2C+gl)*16+o] = fmaxf(red2(acc), 0.f);
    }
}

// ---------- conv3 ----------
__global__ void __launch_bounds__(256) conv3_kernel(const float* __restrict__ w,
        const float* __restrict__ bias){
    __shared__ __align__(16) float xs[143*20+4];
    __shared__ __align__(16) float4 ws4[64*32];
    __shared__ float bsm[32];
    int b = blockIdx.y, l0 = blockIdx.x*128, tid = threadIdx.x;
    for (int i = tid; i < 2048; i += 256){
        int o = i >> 6, tq = i & 63, t = tq >> 2, q = tq & 3;
        float4 v;
        v.x = w[o*256 + (q*4+0)*16 + t];
        v.y = w[o*256 + (q*4+1)*16 + t];
        v.z = w[o*256 + (q*4+2)*16 + t];
        v.w = w[o*256 + (q*4+3)*16 + t];
        ws4[tq*32 + o] = v;
    }
    for (int i = tid; i < 143*16; i += 256){
        int p = i >> 4, c = i & 15, l = l0 + p;
        xs[p*20 + c] = (l < L2C) ? g_y2[(b*L2C+l)*16+c] : 0.f;
    }
    if (tid < 32) bsm[tid] = bias[tid];
    __syncthreads();
    int og = tid & 7, lg = tid >> 3;
    unsigned long long acc[4][4];
    #pragma unroll
    for (int i = 0; i < 4; i++)
        #pragma unroll
        for (int j = 0; j < 4; j++) acc[i][j] = pk2(0.f, 0.f);
    for (int t = 0; t < 16; t++){
        #pragma unroll
        for (int q = 0; q < 4; q++){
            int tq = t*4+q;
            ulonglong2 wv[4], xv[4];
            #pragma unroll
            for (int i = 0; i < 4; i++) wv[i] = *(const ulonglong2*)&ws4[tq*32 + og + i*8];
            #pragma unroll
            for (int j = 0; j < 4; j++) xv[j] = *(const ulonglong2*)&xs[(lg + 32*j + t)*20 + q*4];
            #pragma unroll
            for (int i = 0; i < 4; i++)
                #pragma unroll
                for (int j = 0; j < 4; j++){
                    ffma2(acc[i][j], wv[i].x, xv[j].x);
                    ffma2(acc[i][j], wv[i].y, xv[j].y);
                }
        }
    }
    #pragma unroll
    for (int i = 0; i < 4; i++){
        int o = og + i*8;
        #pragma unroll
        for (int j = 0; j < 4; j++){
            int gl = l0 + lg + 32*j;
            if (gl < L3C)
                g_enc[((size_t)b*L3C+gl)*32+o] = fmaxf(red2(acc[i][j]) + bsm[o], 0.f);
        }
    }
}

// ---------- dec1 persistent: 512 threads ----------
#define D1P_FL (64*WS1+8192+16*XS1+1088+1088+64+256+64)
#define D1P_SMEM (D1P_FL*4)
__global__ void __launch_bounds__(512,1) dec1_persist(const float* __restrict__ attn_w,
        const float* __restrict__ wih, const float* __restrict__ whh,
        const float* __restrict__ bih, const float* __restrict__ bhh){
    extern __shared__ __align__(16) float sm[];
    float* ws   = sm;
    float* aw   = ws + 64*WS1;
    float* xin  = aw + 8192;
    float* gbuf = xin + 16*XS1;
    float* wred = gbuf + 1088;
    float* us   = wred + 1088;
    float* cs   = us + 64;
    float* bs   = cs + 256;
    int tid = threadIdx.x, bid = blockIdx.x;
    int ab = bid >> 1, ah = bid & 1;
    int u0 = (bid & 15)*16, bg = (bid>>4)&3, d = bid>>6, b0 = bg*16;

    const float* wih_d = wih + d*G4*32;
    const float* whh_d = whh + d*G4*HID;
    for (int i = tid; i < 64*288; i += 512){
        int r = i/288, k = i-r*288;
        int gate = (r>>4)*HID + u0 + (r&15);
        ws[r*WS1+k] = (k < 32) ? wih_d[gate*32+k] : whh_d[gate*HID+k-32];
    }
    for (int i = tid; i < 8192; i += 512) aw[i] = attn_w[i];
    if (tid < 64){
        int gate = (tid>>4)*HID + u0 + (tid&15);
        bs[tid] = bih[d*G4+gate] + bhh[d*G4+gate];
    }
    if (tid < 256) cs[tid] = 0.f;
    __syncthreads();

    unsigned bt = 0;
    const float* encb = g_enc + (size_t)ab*(L3C*32);
    int lo = ah*CH, hi = (lo+CH < L3C) ? lo+CH : L3C;
    int chh = tid & 1, lslice = tid >> 1;

    for (int t = 0; t < TDEC; t++){
        const float* hprev = g_h1p[(t+1)&1];
        {   // u = h_prev @ attn_w (8-way K split, float4 loads)
            int dd = tid>>8, rem = tid&255, c = rem&31, kp = rem>>5;
            float acc = 0.f;
            if (t > 0){
                const float4* h4 = (const float4*)(hprev + dd*B_*HID + ab*HID + kp*32);
                const float* awp = aw + kp*32*32 + c;
                #pragma unroll
                for (int k = 0; k < 8; k++){
                    float4 hv = __ldcg(&h4[k]);
                    acc += hv.x*awp[(k*4+0)*32] + hv.y*awp[(k*4+1)*32]
                         + hv.z*awp[(k*4+2)*32] + hv.w*awp[(k*4+3)*32];
                }
            }
            gbuf[tid] = acc;
        }
        // xin h-part fill — depends only on h(t-1); overlap with softmax phase
        for (int i = tid; i < 1024; i += 512){
            int bb = i >> 6, k4 = i & 63;
            float4 v;
            if (t > 0) v = __ldcg((const float4*)&hprev[d*B_*HID+(b0+bb)*HID+k4*4]);
            else       v = make_float4(0.f,0.f,0.f,0.f);
            *(float4*)&xin[bb*XS1 + 32 + k4*4] = v;
        }
        __syncthreads();
        if (tid < 64){
            int dd = tid>>5, c = tid&31;
            float s = 0.f;
            #pragma unroll
            for (int j = 0; j < 8; j++) s += gbuf[dd*256 + j*32 + c];
            us[tid] = s;
        }
        __syncthreads();
        unsigned long long uf[8], ub[8];
        {
            const unsigned long long* ufp = (const unsigned long long*)&us[chh*16];
            const unsigned long long* ubp = (const unsigned long long*)&us[32 + chh*16];
            #pragma unroll
            for (int i = 0; i < 8; i++){ uf[i] = ufp[i]; ub[i] = ubp[i]; }
        }
        float mf = -1e30f, mb = -1e30f, sf = 0.f, sb = 0.f;
        unsigned long long vf2[8], vb2[8];
        #pragma unroll
        for (int i = 0; i < 8; i++){ vf2[i] = pk2(0.f,0.f); vb2[i] = vf2[i]; }
        #pragma unroll 2
        for (int it = 0; it < 8; it++){
            int l = lo + lslice + it*256;
            bool valid = (l < hi);
            ulonglong2 ev2[4];
            if (valid){
                const ulonglong2* e2 = (const ulonglong2*)(encb + l*32 + chh*16);
                #pragma unroll
                for (int j = 0; j < 4; j++) ev2[j] = e2[j];
            } else {
                #pragma unroll
                for (int j = 0; j < 4; j++){ ev2[j].x = 0ull; ev2[j].y = 0ull; }
            }
            unsigned long long dA = pk2(0.f,0.f), dB = dA;
            #pragma unroll
            for (int j = 0; j < 4; j++){
                ffma2(dA, ev2[j].x, uf[2*j]);   ffma2(dA, ev2[j].y, uf[2*j+1]);
                ffma2(dB, ev2[j].x, ub[2*j]);   ffma2(dB, ev2[j].y, ub[2*j+1]);
            }
            float df = red2(dA); df += __shfl_xor_sync(0xffffffffu, df, 1);
            float db = red2(dB); db += __shfl_xor_sync(0xffffffffu, db, 1);
            if (!valid){ df = -1e30f; db = -1e30f; }
            if (df > mf){
                float sc = __expf(mf-df); sf *= sc;
                unsigned long long sc2 = pk2(sc,sc);
                #pragma unroll
                for (int i = 0; i < 8; i++) vf2[i] = mul2(vf2[i], sc2);
                mf = df;
            }
            float pf = __expf(df-mf); sf += pf;
            unsigned long long pf2 = pk2(pf,pf);
            #pragma unroll
            for (int j = 0; j < 4; j++){
                ffma2(vf2[2*j],   pf2, ev2[j].x);
                ffma2(vf2[2*j+1], pf2, ev2[j].y);
            }
            if (db > mb){
                float sc = __expf(mb-db); sb *= sc;
                unsigned long long sc2 = pk2(sc,sc);
                #pragma unroll
                for (int i = 0; i < 8; i++) vb2[i] = mul2(vb2[i], sc2);
                mb = db;
            }
            float pb = __expf(db-mb); sb += pb;
            unsigned long long pb2 = pk2(pb,pb);
            #pragma unroll
            for (int j = 0; j < 4; j++){
                ffma2(vb2[2*j],   pb2, ev2[j].x);
                ffma2(vb2[2*j+1], pb2, ev2[j].y);
            }
        }
        #pragma unroll
        for (int off = 2; off <= 16; off <<= 1){
            float mo = __shfl_xor_sync(0xffffffffu, mf, off);
            float so = __shfl_xor_sync(0xffffffffu, sf, off);
            float M = fmaxf(mf, mo); float ea=__expf(mf-M), eb=__expf(mo-M);
            unsigned long long ea2 = pk2(ea,ea), eb2 = pk2(eb,eb);
            sf = sf*ea + so*eb;
            #pragma unroll
            for (int i = 0; i < 8; i++){
                unsigned long long vo = __shfl_xor_sync(0xffffffffu, vf2[i], off);
                vf2[i] = mul2(vf2[i], ea2); ffma2(vf2[i], eb2, vo);
            }
            mf = M;
            mo = __shfl_xor_sync(0xffffffffu, mb, off);
            so = __shfl_xor_sync(0xffffffffu, sb, off);
            M = fmaxf(mb, mo); ea=__expf(mb-M); eb=__expf(mo-M);
            ea2 = pk2(ea,ea); eb2 = pk2(eb,eb);
            sb = sb*ea + so*eb;
            #pragma unroll
            for (int i = 0; i < 8; i++){
                unsigned long long vo = __shfl_xor_sync(0xffffffffu, vb2[i], off);
                vb2[i] = mul2(vb2[i], ea2); ffma2(vb2[i], eb2, vo);
            }
            mb = M;
        }
        {
            int lane = tid & 31, wq = tid >> 5;
            float* p = wred + wq*68;
            if (lane < 2){
                if (lane == 0){ p[0]=mf; p[1]=sf; p[34]=mb; p[35]=sb; }
                float* v0 = p + 2 + chh*16;
                float* v1 = p + 36 + chh*16;
                #pragma unroll
                for (int i = 0; i < 8; i++){
                    float lo2, hi2;
                    upk2(vf2[i], lo2, hi2); v0[i*2]=lo2; v0[i*2+1]=hi2;
                    upk2(vb2[i], lo2, hi2); v1[i*2]=lo2; v1[i*2+1]=hi2;
                }
            }
        }
        __syncthreads();
        if (tid < 32){
            #pragma unroll
            for (int dir = 0; dir < 2; dir++){
                float M=-1e30f, S=0.f, V=0.f;
                #pragma unroll
                for (int j = 0; j < 16; j++){
                    const float* p = wred + j*68 + dir*34;
                    float mj=p[0], sj=p[1], vj=p[2+tid];
                    float nM=fmaxf(M,mj); float ea=__expf(M-nM), eb=__expf(mj-nM);
                    V=V*ea+vj*eb; S=S*ea+sj*eb; M=nM;
                }
                int pb2i = ((dir*64+ab)*2+ah)*34;
                __stcg(&g_part[pb2i+2+tid], V);
                if (tid == 0){ __stcg(&g_part[pb2i], M); __stcg(&g_part[pb2i+1], S); }
            }
        }
        bt += NBLK; gridbar(&g_bc1, bt);

        // ctx-only fill (h-part already in xin)
        if (tid < 512){
            int bb = tid >> 5, k = tid & 31;
            if (bb < 16){
                int b = b0+bb;
                const float* p0 = &g_part[((d*64+b)*2+0)*34];
                const float* p1 = p0 + 34;
                float m0=__ldcg(p0), s0=__ldcg(p0+1), v0=__ldcg(p0+2+k);
                float m1=__ldcg(p1), s1=__ldcg(p1+1), v1=__ldcg(p1+2+k);
                float M=fmaxf(m0,m1); float e0=__expf(m0-M), e1=__expf(m1-M);
                xin[bb*XS1 + k] = (v0*e0+v1*e1)/(s0*e0+s1*e1);
            }
        }
        __syncthreads();
        if (tid < 256){
            int b = tid & 15, rg = tid >> 4, r0 = rg*4;
            unsigned long long A0 = pk2(bs[r0],   0.f);
            unsigned long long A1 = pk2(bs[r0+1], 0.f);
            unsigned long long A2 = pk2(bs[r0+2], 0.f);
            unsigned long long A3 = pk2(bs[r0+3], 0.f);
            const ulonglong2* w0p = (const ulonglong2*)&ws[r0*WS1];
            const ulonglong2* w1p = (const ulonglong2*)&ws[(r0+1)*WS1];
            const ulonglong2* w2p = (const ulonglong2*)&ws[(r0+2)*WS1];
            const ulonglong2* w3p = (const ulonglong2*)&ws[(r0+3)*WS1];
            const ulonglong2* xp  = (const ulonglong2*)&xin[b*XS1];
            #pragma unroll 8
            for (int k4 = 0; k4 < 72; k4++){
                ulonglong2 xv = xp[k4];
                ulonglong2 wv0=w0p[k4], wv1=w1p[k4], wv2=w2p[k4], wv3=w3p[k4];
                ffma2(A0, wv0.x, xv.x); ffma2(A0, wv0.y, xv.y);
                ffma2(A1, wv1.x, xv.x); ffma2(A1, wv1.y, xv.y);
                ffma2(A2, wv2.x, xv.x); ffma2(A2, wv2.y, xv.y);
                ffma2(A3, wv3.x, xv.x); ffma2(A3, wv3.y, xv.y);
            }
            gbuf[r0*17+b]     = red2(A0);
            gbuf[(r0+1)*17+b] = red2(A1);
            gbuf[(r0+2)*17+b] = red2(A2);
            gbuf[(r0+3)*17+b] = red2(A3);
        }
        __syncthreads();
        if (tid < 256){
            int uu = tid&15, bb = tid>>4;
            float gi=gbuf[uu*17+bb], gf=gbuf[(16+uu)*17+bb];
            float gg=gbuf[(32+uu)*17+bb], go=gbuf[(48+uu)*17+bb];
            float cold = cs[tid];
            float cnew = sigm(gf)*cold + sigm(gi)*tanhf(gg);
            float hnew = sigm(go)*tanhf(cnew);
            cs[tid] = cnew;
            __stcg(&g_h1p[t&1][d*B_*HID+(b0+bb)*HID+u0+uu], hnew);
            int tt = d ? (TDEC-1-t) : t;
            g_d2in[((b0+bb)*TDEC+tt)*512 + d*HID + u0 + uu] = hnew;
        }
        bt += NBLK; gridbar(&g_bc1, bt);
    }
}

// ---------- dec2 persistent ----------
#define D2P_FL (64*WS2+16*XS2+1088+256)
#define D2P_SMEM (D2P_FL*4)
__global__ void __launch_bounds__(256,1) dec2_persist(const float* __restrict__ whh,
        const float* __restrict__ ig, float* __restrict__ outbuf, unsigned* ctr){
    extern __shared__ __align__(16) float sm[];
    float* ws   = sm;
    float* hb   = ws + 64*WS2;
    float* gbuf = hb + 16*XS2;
    float* cs   = gbuf + 1088;
    int tid = threadIdx.x, bid = blockIdx.x;
    int u0 = (bid & 15)*16, bg = (bid>>4)&3, d = bid>>6, b0 = bg*16;
    const float* whh_d = whh + d*G4*HID;
    const float* ig_d  = ig + (size_t)d*(B_*TDEC*G4);
    for (int i = tid; i < 64*256; i += 256){
        int r = i>>8, k = i&255;
        int gate = (r>>4)*HID + u0 + (r&15);
        ws[r*WS2+k] = whh_d[gate*HID+k];
    }
    cs[tid] = 0.f;
    __syncthreads();

    int b = tid & 15, rg = tid >> 4, r0 = rg*4;
    int gbase = (rg>>2)*HID + u0 + (rg&3)*4;

    unsigned bt = 0;
    for (int t = 0; t < TDEC; t++){
        int tt = d ? (TDEC-1-t) : t;
        const float* hprev = g_h2p[(t+1)&1];
        // hoist ig load: overlaps the h-fill + sync latency
        float4 ig4 = __ldcg((const float4*)&ig_d[((size_t)(b0+b)*TDEC+tt)*G4 + gbase]);
        for (int i = tid; i < 16*64; i += 256){
            int bb = i>>6, k4 = i&63;
            float4 v;
            if (t > 0) v = __ldcg((const float4*)&hprev[d*B_*HID+(b0+bb)*HID+k4*4]);
            else       v = make_float4(0.f,0.f,0.f,0.f);
            *(float4*)&hb[bb*XS2 + k4*4] = v;
        }
        __syncthreads();
        unsigned long long A0 = pk2(ig4.x, 0.f);
        unsigned long long A1 = pk2(ig4.y, 0.f);
        unsigned long long A2 = pk2(ig4.z, 0.f);
        unsigned long long A3 = pk2(ig4.w, 0.f);
        const ulonglong2* w0p = (const ulonglong2*)&ws[r0*WS2];
        const ulonglong2* w1p = (const ulonglong2*)&ws[(r0+1)*WS2];
        const ulonglong2* w2p = (const ulonglong2*)&ws[(r0+2)*WS2];
        const ulonglong2* w3p = (const ulonglong2*)&ws[(r0+3)*WS2];
        const ulonglong2* xp  = (const ulonglong2*)&hb[b*XS2];
        #pragma unroll 8
        for (int k4 = 0; k4 < 64; k4++){
            ulonglong2 xv = xp[k4];
            ulonglong2 wv0=w0p[k4], wv1=w1p[k4], wv2=w2p[k4], wv3=w3p[k4];
            ffma2(A0, wv0.x, xv.x); ffma2(A0, wv0.y, xv.y);
            ffma2(A1, wv1.x, xv.x); ffma2(A1, wv1.y, xv.y);
            ffma2(A2, wv2.x, xv.x); ffma2(A2, wv2.y, xv.y);
            ffma2(A3, wv3.x, xv.x); ffma2(A3, wv3.y, xv.y);
        }
        gbuf[r0*17+b]     = red2(A0);
        gbuf[(r0+1)*17+b] = red2(A1);
        gbuf[(r0+2)*17+b] = red2(A2);
        gbuf[(r0+3)*17+b] = red2(A3);
        __syncthreads();
        {
            int uu = tid&15, bb = tid>>4;
            float gi=gbuf[uu*17+bb], gf=gbuf[(16+uu)*17+bb];
            float gg=gbuf[(32+uu)*17+bb], go=gbuf[(48+uu)*17+bb];
            float cold = cs[tid];
            float cnew = sigm(gf)*cold + sigm(gi)*tanhf(gg);
            float hnew = sigm(go)*tanhf(cnew);
            cs[tid] = cnew;
            __stcg(&g_h2p[t&1][d*B_*HID+(b0+bb)*HID+u0+uu], hnew);
            outbuf[((b0+bb)*TDEC+tt)*512 + d*HID + u0 + uu] = hnew;
        }
        bt += NBLK; gridbar(ctr, bt);
    }
}

// ---------- GEMM: z-dim over directions ----------
__global__ void __launch_bounds__(256) gemm_tn(const float* __restrict__ A,
        const float* __restrict__ W, const float* __restrict__ b1,
        const float* __restrict__ b2, float* __restrict__ C, int K, int ldc,
        long wstr, long bstr, long cstr){
    int z = blockIdx.z;
    W  += (size_t)z * wstr;
    b1 += (size_t)z * bstr;
    if (b2) b2 += (size_t)z * bstr;
    C  += (size_t)z * cstr;
    __shared__ __align__(16) float As[16][68];
    __shared__ __align__(16) float Ws[16][68];
    int bm = blockIdx.x*64, bn = blockIdx.y*64;
    int tid = threadIdx.x, tx = tid&15, ty = tid>>4;
    unsigned long long acc[4][2];
    #pragma unroll
    for (int i = 0; i < 4; i++){ acc[i][0]=pk2(0.f,0.f); acc[i][1]=acc[i][0]; }
    for (int k0 = 0; k0 < K; k0 += 16){
        #pragma unroll
        for (int i = tid; i < 1024; i += 256){
            int r = i>>4, c = i&15;
            As[c][r] = A[(size_t)(bm+r)*K + k0 + c];
            Ws[c][r] = W[(size_t)(bn+r)*K + k0 + c];
        }
        __syncthreads();
        #pragma unroll
        for (int k = 0; k < 16; k++){
            float4 av = *(const float4*)&As[k][ty*4];
            float4 wv = *(const float4*)&Ws[k][tx*4];
            unsigned long long w01 = pk2(wv.x, wv.y), w23 = pk2(wv.z, wv.w);
            float aa[4] = {av.x, av.y, av.z, av.w};
            #pragma unroll
            for (int i = 0; i < 4; i++){
                unsigned long long ad = pk2(aa[i], aa[i]);
                ffma2(acc[i][0], ad, w01);
                ffma2(acc[i][1], ad, w23);
            }
        }
        __syncthreads();
    }
    #pragma unroll
    for (int i = 0; i < 4; i++){
        float c0,c1,c2,c3;
        upk2(acc[i][0], c0, c1); upk2(acc[i][1], c2, c3);
        int row = bm + ty*4 + i, col = bn + tx*4;
        float r[4] = {c0,c1,c2,c3};
        #pragma unroll
        for (int j = 0; j < 4; j++){
            float bb = b1[col+j] + (b2 ? b2[col+j] : 0.f);
            C[(size_t)row*ldc + col + j] = r[j] + bb;
        }
    }
}

extern "C" void kernel_launch(void* const* d_in, const int* in_sizes, int n_in,
                              void* d_out, int out_size){
    const float* x       = (const float*)d_in[0];
    const float* conv_w1 = (const float*)d_in[1];
    const float* conv_b1 = (const float*)d_in[2];
    const float* conv_w2 = (const float*)d_in[3];
    const float* conv_b2 = (const float*)d_in[4];
    const float* conv_w3 = (const float*)d_in[5];
    const float* conv_b3 = (const float*)d_in[6];
    const float* attn_w  = (const float*)d_in[7];
    const float* dec1_wih = (const float*)d_in[9];
    const float* dec1_whh = (const float*)d_in[10];
    const float* dec1_bih = (const float*)d_in[11];
    const float* dec1_bhh = (const float*)d_in[12];
    const float* dec2_wih0 = (const float*)d_in[13];
    const float* dec2_whh0 = (const float*)d_in[14];
    const float* dec2_bih0 = (const float*)d_in[15];
    const float* dec2_bhh0 = (const float*)d_in[16];
    const float* dec2_wih1 = (const float*)d_in[17];
    const float* dec2_whh1 = (const float*)d_in[18];
    const float* dec2_bih1 = (const float*)d_in[19];
    const float* dec2_bhh1 = (const float*)d_in[20];
    const float* out_w = (const float*)d_in[21];
    const float* out_b = (const float*)d_in[22];
    float* out = (float*)d_out;

    cudaFuncSetAttribute(dec1_persist, cudaFuncAttributeMaxDynamicSharedMemorySize, D1P_SMEM);
    cudaFuncSetAttribute(dec2_persist, cudaFuncAttributeMaxDynamicSharedMemorySize, D2P_SMEM);

    float *p_d2in, *p_ig, *p_l0, *p_l1;
    unsigned *p_bc2a, *p_bc2b;
    cudaGetSymbolAddress((void**)&p_d2in, g_d2in);
    cudaGetSymbolAddress((void**)&p_ig,   g_ig);
    cudaGetSymbolAddress((void**)&p_l0,   g_l0);
    cudaGetSymbolAddress((void**)&p_l1,   g_l1);
    cudaGetSymbolAddress((void**)&p_bc2a, g_bc2a);
    cudaGetSymbolAddress((void**)&p_bc2b, g_bc2b);

    conv1_kernel<<<dim3(32, B_), 256>>>(x, conv_w1, conv_b1);
    conv2_kernel<<<dim3(16, B_), 256>>>(conv_w2, conv_b2);
    conv3_kernel<<<dim3(32, B_), 256>>>(conv_w3, conv_b3);

    dec1_persist<<<NBLK, 512, D1P_SMEM>>>(attn_w, dec1_wih, dec1_whh, dec1_bih, dec1_bhh);

    gemm_tn<<<dim3(60, 16, 2), 256>>>(p_d2in, dec2_wih0, dec2_bih0, dec2_bhh0,
        p_ig, 512, G4, (long)G4*512, (long)G4, (long)B_*TDEC*G4);
    dec2_persist<<<NBLK, 256, D2P_SMEM>>>(dec2_whh0, p_ig, p_l0, p_bc2a);

    gemm_tn<<<dim3(60, 16, 2), 256>>>(p_l0, dec2_wih1, dec2_bih1, dec2_bhh1,
        p_ig, 512, G4, (long)G4*512, (long)G4, (long)B_*TDEC*G4);
    dec2_persist<<<NBLK, 256, D2P_SMEM>>>(dec2_whh1, p_ig, p_l1, p_bc2b);

    gemm_tn<<<dim3(60, 2, 1), 256>>>(p_l1, out_w, out_b, (const float*)nullptr,
        out, 512, 128, 0L, 0L, 0L);
}